// round 2
// baseline (speedup 1.0000x reference)
#include <cuda_runtime.h>
#include <math.h>

// Shapes (fixed per problem)
#define Bb 4
#define Nn 256
#define Tt 64
#define Dd 128
#define DRr 32
#define DHh 128

// ---------------- scratch (device globals; no allocation allowed) -------------
__device__ float g_q [Bb*Nn*Tt*DHh];     // (b,i,t,h)
__device__ float g_k [Bb*Nn*Tt*DHh];     // (b,j,t,h)
__device__ float g_A [Bb*Nn*Tt*Dd];      // (b,i,t,e)
__device__ float g_Bj[Bb*Nn*Tt*Dd];      // (b,j,t,e)  (becomes Bj+Ej)
__device__ float g_rp[Bb*Nn*Nn*DHh];     // (b,i,j,h)  134MB
__device__ float g_S1[Bb*Tt*Nn*Nn];      // (b,t,i,j)  scores1, then w
__device__ float g_S2[Bb*Nn*Tt*Nn];      // (b,i,t,j)  scores2
__device__ float g_z2[Bb*Nn*Tt*Dd];      // (b,i,t,e)
__device__ float g_P [Bb*Nn*Tt*DRr];     // (b,i,t,r)
__device__ float g_Ct[Bb*Nn*Tt*Dd];      // (b,i,t,e)
__device__ float g_ws[Bb*Nn*Tt];         // (b,i,t)
__device__ float g_SdH[Bb*Nn*Dd];        // (b,j,d)
__device__ float g_Ej[Bb*Nn*Dd];         // (b,j,e)

// ---------------- generic strided-batched SGEMM ------------------------------
// C[m,n] = sum_k A[m,k] * (BT ? B[n,k] : B[k,n]) + bias[n]
// per-batch base offset = (z/div)*s1 + (z%div)*s2
template<bool BT>
__global__ void __launch_bounds__(256) gemm_kernel(
    const float* __restrict__ Ag, long long aS1, long long aS2, int aDiv, int lda,
    const float* __restrict__ Bg, long long bS1, long long bS2, int bDiv, int ldb,
    float*       __restrict__ Cg, long long cS1, long long cS2, int cDiv, int ldc,
    int M, int N, int K, const float* __restrict__ bias)
{
    constexpr int BM = 64, BN = 64, BK = 16;
    __shared__ float As[BK][BM];
    __shared__ float Bs[BK][BN];

    int z = blockIdx.z;
    const float* A = Ag + (long long)(z / aDiv) * aS1 + (long long)(z % aDiv) * aS2;
    const float* B = Bg + (long long)(z / bDiv) * bS1 + (long long)(z % bDiv) * bS2;
    float*       C = Cg + (long long)(z / cDiv) * cS1 + (long long)(z % cDiv) * cS2;

    int bm = blockIdx.y * BM, bn = blockIdx.x * BN;
    int tid = threadIdx.x;
    int tx = tid & 15, ty = tid >> 4;
    int la_m = tid >> 2, la_k = (tid & 3) * 4;

    float acc[4][4] = {};

    for (int k0 = 0; k0 < K; k0 += BK) {
        // ---- load A tile (BM x BK), store transposed As[k][m]
        {
            int m = bm + la_m;
            float4 v = make_float4(0.f, 0.f, 0.f, 0.f);
            if (m < M)
                v = *reinterpret_cast<const float4*>(A + (long long)m * lda + k0 + la_k);
            As[la_k + 0][la_m] = v.x;
            As[la_k + 1][la_m] = v.y;
            As[la_k + 2][la_m] = v.z;
            As[la_k + 3][la_m] = v.w;
        }
        // ---- load B tile
        if (BT) {
            int n = bn + la_m;
            float4 v = make_float4(0.f, 0.f, 0.f, 0.f);
            if (n < N)
                v = *reinterpret_cast<const float4*>(B + (long long)n * ldb + k0 + la_k);
            Bs[la_k + 0][la_m] = v.x;
            Bs[la_k + 1][la_m] = v.y;
            Bs[la_k + 2][la_m] = v.z;
            Bs[la_k + 3][la_m] = v.w;
        } else {
            int kk = k0 + (tid >> 4);
            int n = bn + (tid & 15) * 4;
            float4 v = make_float4(0.f, 0.f, 0.f, 0.f);
            if (n < N)
                v = *reinterpret_cast<const float4*>(B + (long long)kk * ldb + n);
            *reinterpret_cast<float4*>(&Bs[tid >> 4][(tid & 15) * 4]) = v;
        }
        __syncthreads();

        #pragma unroll
        for (int kk = 0; kk < BK; kk++) {
            float4 a = *reinterpret_cast<const float4*>(&As[kk][ty * 4]);
            float4 b = *reinterpret_cast<const float4*>(&Bs[kk][tx * 4]);
            float av[4] = {a.x, a.y, a.z, a.w};
            float bv[4] = {b.x, b.y, b.z, b.w};
            #pragma unroll
            for (int i2 = 0; i2 < 4; i2++)
                #pragma unroll
                for (int j2 = 0; j2 < 4; j2++)
                    acc[i2][j2] += av[i2] * bv[j2];
        }
        __syncthreads();
    }

    #pragma unroll
    for (int i2 = 0; i2 < 4; i2++) {
        int m = bm + ty * 4 + i2;
        if (m >= M) continue;
        #pragma unroll
        for (int j2 = 0; j2 < 4; j2++) {
            int n = bn + tx * 4 + j2;
            if (n >= N) continue;
            float r = acc[i2][j2];
            if (bias) r += bias[n];
            C[(long long)m * ldc + n] = r;
        }
    }
}

// ---------------- delta_H sum over t -----------------------------------------
__global__ void sdh_kernel(const float* __restrict__ dH, float* __restrict__ S)
{
    int bj = blockIdx.x;            // 0..B*N-1
    int d  = threadIdx.x;           // 0..127
    const float* p = dH + (long long)bj * Tt * Dd + d;
    float s = 0.f;
    #pragma unroll 8
    for (int t = 0; t < Tt; t++) s += p[t * Dd];
    S[bj * Dd + d] = s;
}

// ---------------- Bj += Ej (broadcast over t) --------------------------------
__global__ void addej_kernel(float* __restrict__ Bj, const float* __restrict__ Ej, int total)
{
    int idx = blockIdx.x * blockDim.x + threadIdx.x;
    if (idx < total)
        Bj[idx] += Ej[(idx >> 13) * Dd + (idx & 127)];   // idx/(T*D)=b*N+j, idx%D=e
}

// ---------------- softmax over t + diag mask, writes w into S1 ---------------
__global__ void softmax_kernel(float* __restrict__ S1, const float* __restrict__ S2)
{
    int jt = blockIdx.x;   // j-tile of 64
    int i  = blockIdx.y;
    int b  = blockIdx.z;
    __shared__ float v[Tt][65];

    int tid = threadIdx.x;            // 256
    int jl = tid & 63, t0 = tid >> 6; // 4 t-groups of 16
    long long s1base = (long long)b * (Tt * Nn * Nn) + (long long)i * Nn + jt * 64;
    long long s2base = (long long)b * (Nn * Tt * Nn) + (long long)i * (Tt * Nn) + jt * 64;
    const float scale = 0.08838834764831845f;  // 1/sqrt(128)

    #pragma unroll 4
    for (int tt = 0; tt < 16; tt++) {
        int t = t0 * 16 + tt;
        float a = S1[s1base + (long long)t * (Nn * Nn) + jl];
        float c = S2[s2base + (long long)t * Nn + jl];
        v[t][jl] = (a + c) * scale;
    }
    __syncthreads();

    if (tid < 64) {
        int j = jt * 64 + tid;
        float m = -1e30f;
        #pragma unroll 8
        for (int t = 0; t < Tt; t++) m = fmaxf(m, v[t][tid]);
        float s = 0.f;
        #pragma unroll 8
        for (int t = 0; t < Tt; t++) s += expf(v[t][tid] - m);
        float inv = (j == i) ? 0.f : (1.f / s);
        #pragma unroll 8
        for (int t = 0; t < Tt; t++) v[t][tid] = expf(v[t][tid] - m) * inv;
    }
    __syncthreads();

    #pragma unroll 4
    for (int tt = 0; tt < 16; tt++) {
        int t = t0 * 16 + tt;
        S1[s1base + (long long)t * (Nn * Nn) + jl] = v[t][jl];
    }
}

// ---------------- wsum[b,i,t] = sum_j w ---------------------------------------
__global__ void wsum_kernel(const float* __restrict__ W, float* __restrict__ ws)
{
    int idx  = blockIdx.x * 8 + (threadIdx.x >> 5);
    int lane = threadIdx.x & 31;
    int b = idx >> 14, rem = idx & 16383, i = rem >> 6, t = rem & 63;
    const float* p = W + ((long long)(b * Tt + t) * Nn + i) * Nn;
    float s = 0.f;
    #pragma unroll
    for (int c = lane; c < Nn; c += 32) s += p[c];
    #pragma unroll
    for (int o = 16; o; o >>= 1) s += __shfl_xor_sync(0xffffffffu, s, o);
    if (lane == 0) ws[(b * Nn + i) * Tt + t] = s;
}

// ---------------- fused epilogue + LayerNorm ----------------------------------
__global__ void __launch_bounds__(128) final_kernel(
    const float* __restrict__ H,  const float* __restrict__ A,
    const float* __restrict__ z2, const float* __restrict__ Ct,
    const float* __restrict__ ws, const float* __restrict__ bf,
    const float* __restrict__ gamma, const float* __restrict__ beta,
    float* __restrict__ out)
{
    int row = blockIdx.x;
    int e = threadIdx.x;
    long long off = (long long)row * Dd + e;
    float s = ws[row];
    float x = H[off] + (A[off] + bf[e]) * s + z2[off] + Ct[off];

    float sum = x, sq = x * x;
    #pragma unroll
    for (int o = 16; o; o >>= 1) {
        sum += __shfl_xor_sync(0xffffffffu, sum, o);
        sq  += __shfl_xor_sync(0xffffffffu, sq,  o);
    }
    __shared__ float sm[4], sm2[4];
    int w = e >> 5;
    if ((e & 31) == 0) { sm[w] = sum; sm2[w] = sq; }
    __syncthreads();
    sum = sm[0] + sm[1] + sm[2] + sm[3];
    sq  = sm2[0] + sm2[1] + sm2[2] + sm2[3];
    float mu  = sum * (1.f / Dd);
    float var = sq * (1.f / Dd) - mu * mu;
    out[off] = (x - mu) * rsqrtf(var + 1e-5f) * gamma[e] + beta[e];
}

// ---------------- host side ----------------------------------------------------
static void run_gemm(bool bt,
    const float* A, long long aS1, long long aS2, int aDiv, int lda,
    const float* B, long long bS1, long long bS2, int bDiv, int ldb,
    float* C, long long cS1, long long cS2, int cDiv, int ldc,
    int M, int N, int K, const float* bias, int batches)
{
    dim3 g((N + 63) / 64, (M + 63) / 64, batches), blk(256);
    if (bt)
        gemm_kernel<true><<<g, blk>>>(A, aS1, aS2, aDiv, lda, B, bS1, bS2, bDiv, ldb,
                                      C, cS1, cS2, cDiv, ldc, M, N, K, bias);
    else
        gemm_kernel<false><<<g, blk>>>(A, aS1, aS2, aDiv, lda, B, bS1, bS2, bDiv, ldb,
                                       C, cS1, cS2, cDiv, ldc, M, N, K, bias);
}

extern "C" void kernel_launch(void* const* d_in, const int* /*in_sizes*/, int /*n_in*/,
                              void* d_out, int /*out_size*/)
{
    const float* H   = (const float*)d_in[0];
    const float* R   = (const float*)d_in[1];
    const float* dH  = (const float*)d_in[2];
    const float* Wq  = (const float*)d_in[3];
    const float* bq  = (const float*)d_in[4];
    const float* Wk  = (const float*)d_in[5];
    const float* bk  = (const float*)d_in[6];
    const float* Wr  = (const float*)d_in[7];
    const float* br  = (const float*)d_in[8];
    const float* Wf  = (const float*)d_in[9];
    const float* bf  = (const float*)d_in[10];
    const float* gamma = (const float*)d_in[11];
    const float* beta  = (const float*)d_in[12];
    float* out = (float*)d_out;

    // Resolve scratch addresses every call (no static guards; these are
    // non-stream driver queries and are legal during graph capture).
    float *q_p, *k_p, *A_p, *B_p, *rp_p, *S1_p, *S2_p, *z2_p, *P_p, *Ct_p, *ws_p, *SdH_p, *Ej_p;
    cudaGetSymbolAddress((void**)&q_p,  g_q);
    cudaGetSymbolAddress((void**)&k_p,  g_k);
    cudaGetSymbolAddress((void**)&A_p,  g_A);
    cudaGetSymbolAddress((void**)&B_p,  g_Bj);
    cudaGetSymbolAddress((void**)&rp_p, g_rp);
    cudaGetSymbolAddress((void**)&S1_p, g_S1);
    cudaGetSymbolAddress((void**)&S2_p, g_S2);
    cudaGetSymbolAddress((void**)&z2_p, g_z2);
    cudaGetSymbolAddress((void**)&P_p,  g_P);
    cudaGetSymbolAddress((void**)&Ct_p, g_Ct);
    cudaGetSymbolAddress((void**)&ws_p, g_ws);
    cudaGetSymbolAddress((void**)&SdH_p,g_SdH);
    cudaGetSymbolAddress((void**)&Ej_p, g_Ej);

    const int MROW = Bb * Nn * Tt;           // 65536
    const int WFLD = 3 * Dd + DRr;           // 416

    // 1-4. q, k, A, Bj  (H @ W^T)
    run_gemm(true, H,0,0,1,Dd,  Wq,0,0,1,Dd,       q_p,0,0,1,DHh, MROW,DHh,Dd, bq, 1);
    run_gemm(true, H,0,0,1,Dd,  Wk,0,0,1,Dd,       k_p,0,0,1,DHh, MROW,DHh,Dd, bk, 1);
    run_gemm(true, H,0,0,1,Dd,  Wf,0,0,1,WFLD,     A_p,0,0,1,Dd,  MROW,Dd,Dd, nullptr, 1);
    run_gemm(true, H,0,0,1,Dd,  Wf+Dd,0,0,1,WFLD,  B_p,0,0,1,Dd,  MROW,Dd,Dd, nullptr, 1);

    // 5. rproj = R @ Wr^T + br
    run_gemm(true, R,0,0,1,DRr, Wr,0,0,1,DRr, rp_p,0,0,1,DHh, Bb*Nn*Nn,DHh,DRr, br, 1);

    // 6-8. Ej = (sum_t dH) @ W4^T, folded into Bj
    sdh_kernel<<<Bb*Nn, Dd>>>(dH, SdH_p);
    run_gemm(true, SdH_p,0,0,1,Dd, Wf+2*Dd+DRr,0,0,1,WFLD, Ej_p,0,0,1,Dd, Bb*Nn,Dd,Dd, nullptr, 1);
    addej_kernel<<<(Bb*Nn*Tt*Dd)/256, 256>>>(B_p, Ej_p, Bb*Nn*Tt*Dd);

    // 9. S1[b,t,i,j] = q k^T   (batched over b,t)
    run_gemm(true, q_p,(long long)Nn*Tt*DHh,DHh,Tt, Tt*DHh,
                   k_p,(long long)Nn*Tt*DHh,DHh,Tt, Tt*DHh,
                   S1_p,(long long)Nn*Nn,0,1, Nn,
                   Nn,Nn,DHh, nullptr, Bb*Tt);

    // 10. S2[b,i,t,j] = q rproj^T (batched over b,i)
    run_gemm(true, q_p,(long long)Tt*DHh,0,1, DHh,
                   rp_p,(long long)Nn*DHh,0,1, DHh,
                   S2_p,(long long)Tt*Nn,0,1, Nn,
                   Tt,Nn,DHh, nullptr, Bb*Nn);

    // 11. softmax over t, diag mask; w overwrites S1
    softmax_kernel<<<dim3(Nn/64, Nn, Bb), 256>>>(S1_p, S2_p);

    // 12. wsum
    wsum_kernel<<<(Bb*Nn*Tt)/8, 256>>>(S1_p, ws_p);

    // 13. z2[b,i,t,e] = sum_j w * (Bj+Ej)    (batched over b,t)
    run_gemm(false, S1_p,(long long)Nn*Nn,0,1, Nn,
                    B_p,(long long)Nn*Tt*Dd,Dd,Tt, Tt*Dd,
                    z2_p,(long long)Nn*Tt*Dd,Dd,Tt, Tt*Dd,
                    Nn,Dd,Nn, nullptr, Bb*Tt);

    // 14. P[b,i,t,r] = sum_j w * R           (batched over b,i)
    run_gemm(false, S1_p,(long long)Tt*Nn*Nn,Nn,Nn, Nn*Nn,
                    R,(long long)Nn*DRr,0,1, DRr,
                    P_p,(long long)Tt*DRr,0,1, DRr,
                    Tt,DRr,Nn, nullptr, Bb*Nn);

    // 15. Cterm = P @ W3^T
    run_gemm(true, P_p,0,0,1,DRr, Wf+2*Dd,0,0,1,WFLD, Ct_p,0,0,1,Dd, MROW,Dd,DRr, nullptr, 1);

    // 16. fused epilogue + LayerNorm
    final_kernel<<<MROW, Dd>>>(H, A_p, z2_p, Ct_p, ws_p, bf, gamma, beta, out);
}

// round 3
// speedup vs baseline: 1.3420x; 1.3420x over previous
#include <cuda_runtime.h>
#include <math.h>

// Shapes (fixed per problem)
#define Bb 4
#define Nn 256
#define Tt 64
#define Dd 128
#define DRr 32
#define DHh 128

// ---------------- scratch (device globals; no allocation allowed) -------------
__device__ float g_q [Bb*Nn*Tt*DHh];     // (b,i,t,h)
__device__ float g_k [Bb*Nn*Tt*DHh];     // (b,j,t,h)
__device__ float g_A [Bb*Nn*Tt*Dd];      // (b,i,t,e)
__device__ float g_Bj[Bb*Nn*Tt*Dd];      // (b,j,t,e)  (becomes Bj+Ej)
__device__ float g_S1[Bb*Tt*Nn*Nn];      // (b,t,i,j)  scores1, then w
__device__ float g_S2[Bb*Nn*Tt*Nn];      // (b,i,t,j)  scores2
__device__ float g_z2[Bb*Nn*Tt*Dd];      // (b,i,t,e)
__device__ float g_P [Bb*Nn*Tt*DRr];     // (b,i,t,r)
__device__ float g_qr[Bb*Nn*Tt*DRr];     // (b,i,t,r) = q @ Wr
__device__ float g_qb[Bb*Nn*Tt];         // (b,i,t)   = q . br
__device__ float g_Ct[Bb*Nn*Tt*Dd];     // (b,i,t,e)
__device__ float g_ws[Bb*Nn*Tt];         // (b,i,t)
__device__ float g_SdH[Bb*Nn*Dd];        // (b,j,d)
__device__ float g_Ej[Bb*Nn*Dd];         // (b,j,e)

// =============== 128x128x8 SGEMM, 8x8 per thread (exact tiling only) =========
// Requires M%128==0, N%128==0, K%8==0. C = A @ (BT? B^T : B) + bias
template<bool BT>
__global__ void __launch_bounds__(256) gemm128_kernel(
    const float* __restrict__ Ag, long long aS1, long long aS2, int aDiv, int lda,
    const float* __restrict__ Bg, long long bS1, long long bS2, int bDiv, int ldb,
    float*       __restrict__ Cg, long long cS1, long long cS2, int cDiv, int ldc,
    int K, const float* __restrict__ bias)
{
    constexpr int BM = 128, BN = 128, BK = 8;
    __shared__ float As[BK][BM];
    __shared__ float Bs[BK][BN];

    int z = blockIdx.z;
    const float* A = Ag + (long long)(z / aDiv) * aS1 + (long long)(z % aDiv) * aS2;
    const float* B = Bg + (long long)(z / bDiv) * bS1 + (long long)(z % bDiv) * bS2;
    float*       C = Cg + (long long)(z / cDiv) * cS1 + (long long)(z % cDiv) * cS2;

    int bm = blockIdx.y * BM, bn = blockIdx.x * BN;
    int tid = threadIdx.x;
    int tx = tid & 15, ty = tid >> 4;

    int arow = tid >> 1, akc = (tid & 1) * 4;       // A/B(T) tile loads
    const float* Aptr = A + (long long)(bm + arow) * lda + akc;
    const float* Bptr;
    if (BT) Bptr = B + (long long)(bn + arow) * ldb + akc;
    else    Bptr = B + (long long)(tid >> 5) * ldb + bn + (tid & 31) * 4;

    float acc[8][8] = {};

    for (int k0 = 0; k0 < K; k0 += BK) {
        float4 va = *reinterpret_cast<const float4*>(Aptr + k0);
        As[akc + 0][arow] = va.x;
        As[akc + 1][arow] = va.y;
        As[akc + 2][arow] = va.z;
        As[akc + 3][arow] = va.w;
        if (BT) {
            float4 vb = *reinterpret_cast<const float4*>(Bptr + k0);
            Bs[akc + 0][arow] = vb.x;
            Bs[akc + 1][arow] = vb.y;
            Bs[akc + 2][arow] = vb.z;
            Bs[akc + 3][arow] = vb.w;
        } else {
            float4 vb = *reinterpret_cast<const float4*>(Bptr + (long long)k0 * ldb);
            *reinterpret_cast<float4*>(&Bs[tid >> 5][(tid & 31) * 4]) = vb;
        }
        __syncthreads();

        #pragma unroll
        for (int kk = 0; kk < BK; kk++) {
            float a[8], b[8];
            *reinterpret_cast<float4*>(a)     = *reinterpret_cast<const float4*>(&As[kk][ty * 4]);
            *reinterpret_cast<float4*>(a + 4) = *reinterpret_cast<const float4*>(&As[kk][ty * 4 + 64]);
            *reinterpret_cast<float4*>(b)     = *reinterpret_cast<const float4*>(&Bs[kk][tx * 4]);
            *reinterpret_cast<float4*>(b + 4) = *reinterpret_cast<const float4*>(&Bs[kk][tx * 4 + 64]);
            #pragma unroll
            for (int i2 = 0; i2 < 8; i2++)
                #pragma unroll
                for (int j2 = 0; j2 < 8; j2++)
                    acc[i2][j2] += a[i2] * b[j2];
        }
        __syncthreads();
    }

    #pragma unroll
    for (int ih = 0; ih < 2; ih++) {
        #pragma unroll
        for (int i2 = 0; i2 < 4; i2++) {
            int m = bm + ih * 64 + ty * 4 + i2;
            #pragma unroll
            for (int jh = 0; jh < 2; jh++) {
                int n = bn + jh * 64 + tx * 4;
                float4 r;
                r.x = acc[ih * 4 + i2][jh * 4 + 0];
                r.y = acc[ih * 4 + i2][jh * 4 + 1];
                r.z = acc[ih * 4 + i2][jh * 4 + 2];
                r.w = acc[ih * 4 + i2][jh * 4 + 3];
                if (bias) {
                    r.x += bias[n + 0]; r.y += bias[n + 1];
                    r.z += bias[n + 2]; r.w += bias[n + 3];
                }
                *reinterpret_cast<float4*>(C + (long long)m * ldc + n) = r;
            }
        }
    }
}

// =============== 64x64x16 SGEMM, 4x4 per thread (guarded, small shapes) ======
template<bool BT>
__global__ void __launch_bounds__(256) gemm_kernel(
    const float* __restrict__ Ag, long long aS1, long long aS2, int aDiv, int lda,
    const float* __restrict__ Bg, long long bS1, long long bS2, int bDiv, int ldb,
    float*       __restrict__ Cg, long long cS1, long long cS2, int cDiv, int ldc,
    int M, int N, int K, const float* __restrict__ bias)
{
    constexpr int BM = 64, BN = 64, BK = 16;
    __shared__ float As[BK][BM];
    __shared__ float Bs[BK][BN];

    int z = blockIdx.z;
    const float* A = Ag + (long long)(z / aDiv) * aS1 + (long long)(z % aDiv) * aS2;
    const float* B = Bg + (long long)(z / bDiv) * bS1 + (long long)(z % bDiv) * bS2;
    float*       C = Cg + (long long)(z / cDiv) * cS1 + (long long)(z % cDiv) * cS2;

    int bm = blockIdx.y * BM, bn = blockIdx.x * BN;
    int tid = threadIdx.x;
    int tx = tid & 15, ty = tid >> 4;
    int la_m = tid >> 2, la_k = (tid & 3) * 4;

    float acc[4][4] = {};

    for (int k0 = 0; k0 < K; k0 += BK) {
        {
            int m = bm + la_m;
            float4 v = make_float4(0.f, 0.f, 0.f, 0.f);
            if (m < M)
                v = *reinterpret_cast<const float4*>(A + (long long)m * lda + k0 + la_k);
            As[la_k + 0][la_m] = v.x;
            As[la_k + 1][la_m] = v.y;
            As[la_k + 2][la_m] = v.z;
            As[la_k + 3][la_m] = v.w;
        }
        if (BT) {
            int n = bn + la_m;
            float4 v = make_float4(0.f, 0.f, 0.f, 0.f);
            if (n < N)
                v = *reinterpret_cast<const float4*>(B + (long long)n * ldb + k0 + la_k);
            Bs[la_k + 0][la_m] = v.x;
            Bs[la_k + 1][la_m] = v.y;
            Bs[la_k + 2][la_m] = v.z;
            Bs[la_k + 3][la_m] = v.w;
        } else {
            int kk = k0 + (tid >> 4);
            int n = bn + (tid & 15) * 4;
            float4 v = make_float4(0.f, 0.f, 0.f, 0.f);
            if (n < N)
                v = *reinterpret_cast<const float4*>(B + (long long)kk * ldb + n);
            *reinterpret_cast<float4*>(&Bs[tid >> 4][(tid & 15) * 4]) = v;
        }
        __syncthreads();

        #pragma unroll
        for (int kk = 0; kk < BK; kk++) {
            float4 a = *reinterpret_cast<const float4*>(&As[kk][ty * 4]);
            float4 b = *reinterpret_cast<const float4*>(&Bs[kk][tx * 4]);
            float av[4] = {a.x, a.y, a.z, a.w};
            float bv[4] = {b.x, b.y, b.z, b.w};
            #pragma unroll
            for (int i2 = 0; i2 < 4; i2++)
                #pragma unroll
                for (int j2 = 0; j2 < 4; j2++)
                    acc[i2][j2] += av[i2] * bv[j2];
        }
        __syncthreads();
    }

    #pragma unroll
    for (int i2 = 0; i2 < 4; i2++) {
        int m = bm + ty * 4 + i2;
        if (m >= M) continue;
        #pragma unroll
        for (int j2 = 0; j2 < 4; j2++) {
            int n = bn + tx * 4 + j2;
            if (n >= N) continue;
            float r = acc[i2][j2];
            if (bias) r += bias[n];
            C[(long long)m * ldc + n] = r;
        }
    }
}

// ---------------- delta_H sum over t -----------------------------------------
__global__ void sdh_kernel(const float* __restrict__ dH, float* __restrict__ S)
{
    int bj = blockIdx.x;
    int d  = threadIdx.x;
    const float* p = dH + (long long)bj * Tt * Dd + d;
    float s = 0.f;
    #pragma unroll 8
    for (int t = 0; t < Tt; t++) s += p[t * Dd];
    S[bj * Dd + d] = s;
}

// ---------------- Bj += Ej (broadcast over t) --------------------------------
__global__ void addej_kernel(float* __restrict__ Bj, const float* __restrict__ Ej, int total)
{
    int idx = blockIdx.x * blockDim.x + threadIdx.x;
    if (idx < total)
        Bj[idx] += Ej[(idx >> 13) * Dd + (idx & 127)];
}

// ---------------- qb[m] = dot(q[m,:], br) -------------------------------------
__global__ void qb_kernel(const float* __restrict__ q, const float* __restrict__ br,
                          float* __restrict__ qb)
{
    int row  = blockIdx.x * 8 + (threadIdx.x >> 5);
    int lane = threadIdx.x & 31;
    float4 v = *reinterpret_cast<const float4*>(q + (long long)row * DHh + lane * 4);
    float4 w = *reinterpret_cast<const float4*>(br + lane * 4);
    float s = v.x * w.x + v.y * w.y + v.z * w.z + v.w * w.w;
    #pragma unroll
    for (int o = 16; o; o >>= 1) s += __shfl_xor_sync(0xffffffffu, s, o);
    if (lane == 0) qb[row] = s;
}

// ---------------- softmax over t + diag mask, writes w into S1 ---------------
__global__ void softmax_kernel(float* __restrict__ S1, const float* __restrict__ S2,
                               const float* __restrict__ qb)
{
    int jt = blockIdx.x;   // j-tile of 64
    int i  = blockIdx.y;
    int b  = blockIdx.z;
    __shared__ float v[Tt][65];

    int tid = threadIdx.x;            // 256
    int jl = tid & 63, t0 = tid >> 6;
    long long s1base = (long long)b * (Tt * Nn * Nn) + (long long)i * Nn + jt * 64;
    long long s2base = (long long)b * (Nn * Tt * Nn) + (long long)i * (Tt * Nn) + jt * 64;
    long long qbbase = (long long)(b * Nn + i) * Tt;
    const float scale = 0.08838834764831845f;  // 1/sqrt(128)

    #pragma unroll 4
    for (int tt = 0; tt < 16; tt++) {
        int t = t0 * 16 + tt;
        float a = S1[s1base + (long long)t * (Nn * Nn) + jl];
        float c = S2[s2base + (long long)t * Nn + jl];
        v[t][jl] = (a + c + qb[qbbase + t]) * scale;
    }
    __syncthreads();

    if (tid < 64) {
        int j = jt * 64 + tid;
        float m = -1e30f;
        #pragma unroll 8
        for (int t = 0; t < Tt; t++) m = fmaxf(m, v[t][tid]);
        float s = 0.f;
        #pragma unroll 8
        for (int t = 0; t < Tt; t++) s += expf(v[t][tid] - m);
        float inv = (j == i) ? 0.f : (1.f / s);
        #pragma unroll 8
        for (int t = 0; t < Tt; t++) v[t][tid] = expf(v[t][tid] - m) * inv;
    }
    __syncthreads();

    #pragma unroll 4
    for (int tt = 0; tt < 16; tt++) {
        int t = t0 * 16 + tt;
        S1[s1base + (long long)t * (Nn * Nn) + jl] = v[t][jl];
    }
}

// ---------------- wsum[b,i,t] = sum_j w ---------------------------------------
__global__ void wsum_kernel(const float* __restrict__ W, float* __restrict__ ws)
{
    int idx  = blockIdx.x * 8 + (threadIdx.x >> 5);
    int lane = threadIdx.x & 31;
    int b = idx >> 14, rem = idx & 16383, i = rem >> 6, t = rem & 63;
    const float* p = W + ((long long)(b * Tt + t) * Nn + i) * Nn;
    float s = 0.f;
    #pragma unroll
    for (int c = lane; c < Nn; c += 32) s += p[c];
    #pragma unroll
    for (int o = 16; o; o >>= 1) s += __shfl_xor_sync(0xffffffffu, s, o);
    if (lane == 0) ws[(b * Nn + i) * Tt + t] = s;
}

// ---------------- fused epilogue + LayerNorm ----------------------------------
__global__ void __launch_bounds__(128) final_kernel(
    const float* __restrict__ H,  const float* __restrict__ A,
    const float* __restrict__ z2, const float* __restrict__ Ct,
    const float* __restrict__ ws, const float* __restrict__ bf,
    const float* __restrict__ gamma, const float* __restrict__ beta,
    float* __restrict__ out)
{
    int row = blockIdx.x;
    int e = threadIdx.x;
    long long off = (long long)row * Dd + e;
    float s = ws[row];
    float x = H[off] + (A[off] + bf[e]) * s + z2[off] + Ct[off];

    float sum = x, sq = x * x;
    #pragma unroll
    for (int o = 16; o; o >>= 1) {
        sum += __shfl_xor_sync(0xffffffffu, sum, o);
        sq  += __shfl_xor_sync(0xffffffffu, sq,  o);
    }
    __shared__ float sm[4], sm2[4];
    int w = e >> 5;
    if ((e & 31) == 0) { sm[w] = sum; sm2[w] = sq; }
    __syncthreads();
    sum = sm[0] + sm[1] + sm[2] + sm[3];
    sq  = sm2[0] + sm2[1] + sm2[2] + sm2[3];
    float mu  = sum * (1.f / Dd);
    float var = sq * (1.f / Dd) - mu * mu;
    out[off] = (x - mu) * rsqrtf(var + 1e-5f) * gamma[e] + beta[e];
}

// ---------------- host helpers -------------------------------------------------
static void run_gemm128(bool bt,
    const float* A, long long aS1, long long aS2, int aDiv, int lda,
    const float* B, long long bS1, long long bS2, int bDiv, int ldb,
    float* C, long long cS1, long long cS2, int cDiv, int ldc,
    int M, int N, int K, const float* bias, int batches)
{
    dim3 g(N / 128, M / 128, batches), blk(256);
    if (bt)
        gemm128_kernel<true><<<g, blk>>>(A, aS1, aS2, aDiv, lda, B, bS1, bS2, bDiv, ldb,
                                         C, cS1, cS2, cDiv, ldc, K, bias);
    else
        gemm128_kernel<false><<<g, blk>>>(A, aS1, aS2, aDiv, lda, B, bS1, bS2, bDiv, ldb,
                                          C, cS1, cS2, cDiv, ldc, K, bias);
}

static void run_gemm64(bool bt,
    const float* A, long long aS1, long long aS2, int aDiv, int lda,
    const float* B, long long bS1, long long bS2, int bDiv, int ldb,
    float* C, long long cS1, long long cS2, int cDiv, int ldc,
    int M, int N, int K, const float* bias, int batches)
{
    dim3 g((N + 63) / 64, (M + 63) / 64, batches), blk(256);
    if (bt)
        gemm_kernel<true><<<g, blk>>>(A, aS1, aS2, aDiv, lda, B, bS1, bS2, bDiv, ldb,
                                      C, cS1, cS2, cDiv, ldc, M, N, K, bias);
    else
        gemm_kernel<false><<<g, blk>>>(A, aS1, aS2, aDiv, lda, B, bS1, bS2, bDiv, ldb,
                                       C, cS1, cS2, cDiv, ldc, M, N, K, bias);
}

extern "C" void kernel_launch(void* const* d_in, const int* /*in_sizes*/, int /*n_in*/,
                              void* d_out, int /*out_size*/)
{
    const float* H   = (const float*)d_in[0];
    const float* R   = (const float*)d_in[1];
    const float* dH  = (const float*)d_in[2];
    const float* Wq  = (const float*)d_in[3];
    const float* bq  = (const float*)d_in[4];
    const float* Wk  = (const float*)d_in[5];
    const float* bk  = (const float*)d_in[6];
    const float* Wr  = (const float*)d_in[7];
    const float* br  = (const float*)d_in[8];
    const float* Wf  = (const float*)d_in[9];
    const float* bf  = (const float*)d_in[10];
    const float* gamma = (const float*)d_in[11];
    const float* beta  = (const float*)d_in[12];
    float* out = (float*)d_out;

    float *q_p, *k_p, *A_p, *B_p, *S1_p, *S2_p, *z2_p, *P_p, *qr_p, *qb_p, *Ct_p, *ws_p, *SdH_p, *Ej_p;
    cudaGetSymbolAddress((void**)&q_p,  g_q);
    cudaGetSymbolAddress((void**)&k_p,  g_k);
    cudaGetSymbolAddress((void**)&A_p,  g_A);
    cudaGetSymbolAddress((void**)&B_p,  g_Bj);
    cudaGetSymbolAddress((void**)&S1_p, g_S1);
    cudaGetSymbolAddress((void**)&S2_p, g_S2);
    cudaGetSymbolAddress((void**)&z2_p, g_z2);
    cudaGetSymbolAddress((void**)&P_p,  g_P);
    cudaGetSymbolAddress((void**)&qr_p, g_qr);
    cudaGetSymbolAddress((void**)&qb_p, g_qb);
    cudaGetSymbolAddress((void**)&Ct_p, g_Ct);
    cudaGetSymbolAddress((void**)&ws_p, g_ws);
    cudaGetSymbolAddress((void**)&SdH_p,g_SdH);
    cudaGetSymbolAddress((void**)&Ej_p, g_Ej);

    const int MROW = Bb * Nn * Tt;           // 65536
    const int WFLD = 3 * Dd + DRr;           // 416

    // 1-4. q, k, A, Bj  (H @ W^T)
    run_gemm128(true, H,0,0,1,Dd,  Wq,0,0,1,Dd,       q_p,0,0,1,DHh, MROW,DHh,Dd, bq, 1);
    run_gemm128(true, H,0,0,1,Dd,  Wk,0,0,1,Dd,       k_p,0,0,1,DHh, MROW,DHh,Dd, bk, 1);
    run_gemm128(true, H,0,0,1,Dd,  Wf,0,0,1,WFLD,     A_p,0,0,1,Dd,  MROW,Dd,Dd, nullptr, 1);
    run_gemm128(true, H,0,0,1,Dd,  Wf+Dd,0,0,1,WFLD,  B_p,0,0,1,Dd,  MROW,Dd,Dd, nullptr, 1);

    // 5. qr = q @ Wr  (non-T: B[k=h][n=r]),  qb = q . br
    run_gemm64(false, q_p,0,0,1,DHh, Wr,0,0,1,DRr, qr_p,0,0,1,DRr, MROW,DRr,DHh, nullptr, 1);
    qb_kernel<<<MROW/8, 256>>>(q_p, br, qb_p);

    // 6-8. Ej = (sum_t dH) @ W4^T, folded into Bj
    sdh_kernel<<<Bb*Nn, Dd>>>(dH, SdH_p);
    run_gemm128(true, SdH_p,0,0,1,Dd, Wf+2*Dd+DRr,0,0,1,WFLD, Ej_p,0,0,1,Dd, Bb*Nn,Dd,Dd, nullptr, 1);
    addej_kernel<<<(Bb*Nn*Tt*Dd)/256, 256>>>(B_p, Ej_p, Bb*Nn*Tt*Dd);

    // 9. S1[b,t,i,j] = q k^T   (batched over b,t)
    run_gemm128(true, q_p,(long long)Nn*Tt*DHh,DHh,Tt, Tt*DHh,
                      k_p,(long long)Nn*Tt*DHh,DHh,Tt, Tt*DHh,
                      S1_p,(long long)Nn*Nn,0,1, Nn,
                      Nn,Nn,DHh, nullptr, Bb*Tt);

    // 10. S2[b,i,t,j] = qr @ R^T (batched over b,i)
    run_gemm64(true, qr_p,(long long)Tt*DRr,0,1, DRr,
                     R,(long long)Nn*DRr,0,1, DRr,
                     S2_p,(long long)Tt*Nn,0,1, Nn,
                     Tt,Nn,DRr, nullptr, Bb*Nn);

    // 11. softmax over t (adds qb), diag mask; w overwrites S1
    softmax_kernel<<<dim3(Nn/64, Nn, Bb), 256>>>(S1_p, S2_p, qb_p);

    // 12. wsum
    wsum_kernel<<<(Bb*Nn*Tt)/8, 256>>>(S1_p, ws_p);

    // 13. z2[b,i,t,e] = sum_j w * (Bj+Ej)    (batched over b,t)
    run_gemm128(false, S1_p,(long long)Nn*Nn,0,1, Nn,
                       B_p,(long long)Nn*Tt*Dd,Dd,Tt, Tt*Dd,
                       z2_p,(long long)Nn*Tt*Dd,Dd,Tt, Tt*Dd,
                       Nn,Dd,Nn, nullptr, Bb*Tt);

    // 14. P[b,i,t,r] = sum_j w * R           (batched over b,i)
    run_gemm64(false, S1_p,(long long)Tt*Nn*Nn,Nn,Nn, Nn*Nn,
                      R,(long long)Nn*DRr,0,1, DRr,
                      P_p,(long long)Tt*DRr,0,1, DRr,
                      Tt,DRr,Nn, nullptr, Bb*Nn);

    // 15. Cterm = P @ W3^T
    run_gemm128(true, P_p,0,0,1,DRr, Wf+2*Dd,0,0,1,WFLD, Ct_p,0,0,1,Dd, MROW,Dd,DRr, nullptr, 1);

    // 16. fused epilogue + LayerNorm
    final_kernel<<<MROW, Dd>>>(H, A_p, z2_p, Ct_p, ws_p, bf, gamma, beta, out);
}

// round 4
// speedup vs baseline: 2.0135x; 1.5003x over previous
#include <cuda_runtime.h>
#include <math.h>
#include <stdint.h>

// Shapes (fixed per problem)
#define Bb 4
#define Nn 256
#define Tt 64
#define Dd 128
#define DRr 32
#define DHh 128

// ---------------- scratch (device globals; no allocation allowed) -------------
__device__ float g_q [Bb*Nn*Tt*DHh];     // (b,i,t,h)
__device__ float g_k [Bb*Nn*Tt*DHh];     // (b,j,t,h)
__device__ float g_A [Bb*Nn*Tt*Dd];      // (b,i,t,e)
__device__ float g_Bj[Bb*Nn*Tt*Dd];      // (b,j,t,e)  (becomes Bj+Ej)
__device__ float g_S1[Bb*Tt*Nn*Nn];      // (b,t,i,j)  scores1, then w
__device__ float g_S2[Bb*Nn*Tt*Nn];      // (b,i,t,j)  scores2
__device__ float g_z2[Bb*Nn*Tt*Dd];      // (b,i,t,e)
__device__ float g_P [Bb*Nn*Tt*DRr];     // (b,i,t,r)
__device__ float g_qr[Bb*Nn*Tt*DRr];     // (b,i,t,r) = q @ Wr
__device__ float g_qb[Bb*Nn*Tt];         // (b,i,t)   = q . br
__device__ float g_Ct[Bb*Nn*Tt*Dd];      // (b,i,t,e)
__device__ float g_ws[Bb*Nn*Tt];         // (b,i,t)
__device__ float g_SdH[Bb*Nn*Dd];        // (b,j,d)
__device__ float g_Ej[Bb*Nn*Dd];         // (b,j,e)

// ---------------- tf32 helpers -------------------------------------------------
__device__ __forceinline__ uint32_t f2tf(float x) {
    uint32_t r;
    asm("cvt.rna.tf32.f32 %0, %1;" : "=r"(r) : "f"(x));
    return r;
}

__device__ __forceinline__ void mma_tf32(float* d, const uint32_t* a, const uint32_t* b) {
    asm volatile(
        "mma.sync.aligned.m16n8k8.row.col.f32.tf32.tf32.f32 "
        "{%0,%1,%2,%3}, {%4,%5,%6,%7}, {%8,%9}, {%0,%1,%2,%3};"
        : "+f"(d[0]), "+f"(d[1]), "+f"(d[2]), "+f"(d[3])
        : "r"(a[0]), "r"(a[1]), "r"(a[2]), "r"(a[3]), "r"(b[0]), "r"(b[1]));
}

// =============== 128x128xK TF32 tensor-core GEMM ==============================
// Requires M%128==0, N%128==0, K%32==0. C = A @ (BT? B^T : B) + bias
// 8 warps (2x4): warp tile 64x32, mma m16n8k8.
template<bool BT>
__global__ void __launch_bounds__(256) gemm_tf32_kernel(
    const float* __restrict__ Ag, long long aS1, long long aS2, int aDiv, int lda,
    const float* __restrict__ Bg, long long bS1, long long bS2, int bDiv, int ldb,
    float*       __restrict__ Cg, long long cS1, long long cS2, int cDiv, int ldc,
    int K, const float* __restrict__ bias)
{
    constexpr int BK = 32;
    __shared__ uint32_t As[128 * 36];  // A: [row][k], stride 36
    __shared__ uint32_t Bs[128 * 36];  // BT: [n][k] stride 36 ; nonT: [k][n] stride 136

    int z = blockIdx.z;
    const float* A = Ag + (long long)(z / aDiv) * aS1 + (long long)(z % aDiv) * aS2;
    const float* B = Bg + (long long)(z / bDiv) * bS1 + (long long)(z % bDiv) * bS2;
    float*       C = Cg + (long long)(z / cDiv) * cS1 + (long long)(z % cDiv) * cS2;

    int bm = blockIdx.y * 128, bn = blockIdx.x * 128;
    int tid  = threadIdx.x;
    int warp = tid >> 5, lane = tid & 31;
    int gid = lane >> 2, tig = lane & 3;
    int wm = (warp & 1) * 64;       // warp M offset within CTA tile
    int wn = (warp >> 1) * 32;      // warp N offset

    // loader indices
    int lr = tid >> 3;              // 0..31  (row within pass)
    int lc = (tid & 7) * 4;         // 0..28  (k quad)
    int kr = tid >> 5;              // 0..7   (nonT B: k within pass)
    int nc = (tid & 31) * 4;        // 0..124 (nonT B: n quad)

    float acc[4][4][4] = {};

    for (int k0 = 0; k0 < K; k0 += BK) {
        // ---- A tile: 128 x 32, 4 passes of 32 rows
        #pragma unroll
        for (int p = 0; p < 4; p++) {
            int row = p * 32 + lr;
            float4 v = *reinterpret_cast<const float4*>(A + (long long)(bm + row) * lda + k0 + lc);
            As[row * 36 + lc + 0] = f2tf(v.x);
            As[row * 36 + lc + 1] = f2tf(v.y);
            As[row * 36 + lc + 2] = f2tf(v.z);
            As[row * 36 + lc + 3] = f2tf(v.w);
        }
        // ---- B tile
        if (BT) {
            #pragma unroll
            for (int p = 0; p < 4; p++) {
                int n = p * 32 + lr;
                float4 v = *reinterpret_cast<const float4*>(B + (long long)(bn + n) * ldb + k0 + lc);
                Bs[n * 36 + lc + 0] = f2tf(v.x);
                Bs[n * 36 + lc + 1] = f2tf(v.y);
                Bs[n * 36 + lc + 2] = f2tf(v.z);
                Bs[n * 36 + lc + 3] = f2tf(v.w);
            }
        } else {
            #pragma unroll
            for (int p = 0; p < 4; p++) {
                int kk = p * 8 + kr;
                float4 v = *reinterpret_cast<const float4*>(B + (long long)(k0 + kk) * ldb + bn + nc);
                Bs[kk * 136 + nc + 0] = f2tf(v.x);
                Bs[kk * 136 + nc + 1] = f2tf(v.y);
                Bs[kk * 136 + nc + 2] = f2tf(v.z);
                Bs[kk * 136 + nc + 3] = f2tf(v.w);
            }
        }
        __syncthreads();

        #pragma unroll
        for (int ks = 0; ks < 4; ks++) {
            uint32_t af[4][4];
            #pragma unroll
            for (int mi = 0; mi < 4; mi++) {
                int r0 = wm + mi * 16 + gid;
                af[mi][0] = As[r0 * 36 + ks * 8 + tig];
                af[mi][1] = As[(r0 + 8) * 36 + ks * 8 + tig];
                af[mi][2] = As[r0 * 36 + ks * 8 + tig + 4];
                af[mi][3] = As[(r0 + 8) * 36 + ks * 8 + tig + 4];
            }
            uint32_t bf[4][2];
            #pragma unroll
            for (int ni = 0; ni < 4; ni++) {
                int n0 = wn + ni * 8 + gid;
                if (BT) {
                    bf[ni][0] = Bs[n0 * 36 + ks * 8 + tig];
                    bf[ni][1] = Bs[n0 * 36 + ks * 8 + tig + 4];
                } else {
                    bf[ni][0] = Bs[(ks * 8 + tig) * 136 + n0];
                    bf[ni][1] = Bs[(ks * 8 + tig + 4) * 136 + n0];
                }
            }
            #pragma unroll
            for (int mi = 0; mi < 4; mi++)
                #pragma unroll
                for (int ni = 0; ni < 4; ni++)
                    mma_tf32(acc[mi][ni], af[mi], bf[ni]);
        }
        __syncthreads();
    }

    // ---- epilogue
    #pragma unroll
    for (int mi = 0; mi < 4; mi++) {
        int row0 = bm + wm + mi * 16 + gid;
        #pragma unroll
        for (int ni = 0; ni < 4; ni++) {
            int col = bn + wn + ni * 8 + tig * 2;
            float2 v0 = make_float2(acc[mi][ni][0], acc[mi][ni][1]);
            float2 v1 = make_float2(acc[mi][ni][2], acc[mi][ni][3]);
            if (bias) {
                float b0 = bias[col], b1 = bias[col + 1];
                v0.x += b0; v0.y += b1;
                v1.x += b0; v1.y += b1;
            }
            *reinterpret_cast<float2*>(C + (long long)row0 * ldc + col) = v0;
            *reinterpret_cast<float2*>(C + (long long)(row0 + 8) * ldc + col) = v1;
        }
    }
}

// =============== 64x64x16 fp32 SGEMM (guarded, small shapes) ==================
template<bool BT>
__global__ void __launch_bounds__(256) gemm_kernel(
    const float* __restrict__ Ag, long long aS1, long long aS2, int aDiv, int lda,
    const float* __restrict__ Bg, long long bS1, long long bS2, int bDiv, int ldb,
    float*       __restrict__ Cg, long long cS1, long long cS2, int cDiv, int ldc,
    int M, int N, int K, const float* __restrict__ bias)
{
    constexpr int BM = 64, BN = 64, BK = 16;
    __shared__ float As[BK][BM];
    __shared__ float Bs[BK][BN];

    int z = blockIdx.z;
    const float* A = Ag + (long long)(z / aDiv) * aS1 + (long long)(z % aDiv) * aS2;
    const float* B = Bg + (long long)(z / bDiv) * bS1 + (long long)(z % bDiv) * bS2;
    float*       C = Cg + (long long)(z / cDiv) * cS1 + (long long)(z % cDiv) * cS2;

    int bm = blockIdx.y * BM, bn = blockIdx.x * BN;
    int tid = threadIdx.x;
    int tx = tid & 15, ty = tid >> 4;
    int la_m = tid >> 2, la_k = (tid & 3) * 4;

    float acc[4][4] = {};

    for (int k0 = 0; k0 < K; k0 += BK) {
        {
            int m = bm + la_m;
            float4 v = make_float4(0.f, 0.f, 0.f, 0.f);
            if (m < M)
                v = *reinterpret_cast<const float4*>(A + (long long)m * lda + k0 + la_k);
            As[la_k + 0][la_m] = v.x;
            As[la_k + 1][la_m] = v.y;
            As[la_k + 2][la_m] = v.z;
            As[la_k + 3][la_m] = v.w;
        }
        if (BT) {
            int n = bn + la_m;
            float4 v = make_float4(0.f, 0.f, 0.f, 0.f);
            if (n < N)
                v = *reinterpret_cast<const float4*>(B + (long long)n * ldb + k0 + la_k);
            Bs[la_k + 0][la_m] = v.x;
            Bs[la_k + 1][la_m] = v.y;
            Bs[la_k + 2][la_m] = v.z;
            Bs[la_k + 3][la_m] = v.w;
        } else {
            int kk = k0 + (tid >> 4);
            int n = bn + (tid & 15) * 4;
            float4 v = make_float4(0.f, 0.f, 0.f, 0.f);
            if (n < N)
                v = *reinterpret_cast<const float4*>(B + (long long)kk * ldb + n);
            *reinterpret_cast<float4*>(&Bs[tid >> 4][(tid & 15) * 4]) = v;
        }
        __syncthreads();

        #pragma unroll
        for (int kk = 0; kk < BK; kk++) {
            float4 a = *reinterpret_cast<const float4*>(&As[kk][ty * 4]);
            float4 b = *reinterpret_cast<const float4*>(&Bs[kk][tx * 4]);
            float av[4] = {a.x, a.y, a.z, a.w};
            float bv[4] = {b.x, b.y, b.z, b.w};
            #pragma unroll
            for (int i2 = 0; i2 < 4; i2++)
                #pragma unroll
                for (int j2 = 0; j2 < 4; j2++)
                    acc[i2][j2] += av[i2] * bv[j2];
        }
        __syncthreads();
    }

    #pragma unroll
    for (int i2 = 0; i2 < 4; i2++) {
        int m = bm + ty * 4 + i2;
        if (m >= M) continue;
        #pragma unroll
        for (int j2 = 0; j2 < 4; j2++) {
            int n = bn + tx * 4 + j2;
            if (n >= N) continue;
            float r = acc[i2][j2];
            if (bias) r += bias[n];
            C[(long long)m * ldc + n] = r;
        }
    }
}

// ---------------- delta_H sum over t -----------------------------------------
__global__ void sdh_kernel(const float* __restrict__ dH, float* __restrict__ S)
{
    int bj = blockIdx.x;
    int d  = threadIdx.x;
    const float* p = dH + (long long)bj * Tt * Dd + d;
    float s = 0.f;
    #pragma unroll 8
    for (int t = 0; t < Tt; t++) s += p[t * Dd];
    S[bj * Dd + d] = s;
}

// ---------------- Bj += Ej (broadcast over t) --------------------------------
__global__ void addej_kernel(float* __restrict__ Bj, const float* __restrict__ Ej, int total)
{
    int idx = blockIdx.x * blockDim.x + threadIdx.x;
    if (idx < total)
        Bj[idx] += Ej[(idx >> 13) * Dd + (idx & 127)];
}

// ---------------- qb[m] = dot(q[m,:], br) -------------------------------------
__global__ void qb_kernel(const float* __restrict__ q, const float* __restrict__ br,
                          float* __restrict__ qb)
{
    int row  = blockIdx.x * 8 + (threadIdx.x >> 5);
    int lane = threadIdx.x & 31;
    float4 v = *reinterpret_cast<const float4*>(q + (long long)row * DHh + lane * 4);
    float4 w = *reinterpret_cast<const float4*>(br + lane * 4);
    float s = v.x * w.x + v.y * w.y + v.z * w.z + v.w * w.w;
    #pragma unroll
    for (int o = 16; o; o >>= 1) s += __shfl_xor_sync(0xffffffffu, s, o);
    if (lane == 0) qb[row] = s;
}

// ---- fused softmax over t + diag mask + wsum; w overwrites S1 ----------------
// One block per (i, b); thread j owns column j, all 64 t-values in registers.
__global__ void __launch_bounds__(256) softmax_fused_kernel(
    float* __restrict__ S1, const float* __restrict__ S2,
    const float* __restrict__ qb, float* __restrict__ ws)
{
    int i = blockIdx.x, b = blockIdx.y;
    int j = threadIdx.x;               // 0..255
    int warp = j >> 5, lane = j & 31;

    __shared__ float qbs[Tt];
    __shared__ float part[8][Tt];

    long long qbbase = (long long)(b * Nn + i) * Tt;
    if (j < Tt) qbs[j] = qb[qbbase + j];
    __syncthreads();

    long long s1base = (long long)b * (Tt * Nn * Nn) + (long long)i * Nn + j;
    long long s2base = (long long)(b * Nn + i) * (Tt * Nn) + j;
    const float scale = 0.08838834764831845f;   // 1/sqrt(128)

    float vals[Tt];
    float m = -1e30f;
    #pragma unroll 8
    for (int t = 0; t < Tt; t++) {
        float v = S1[s1base + (long long)t * (Nn * Nn)] + S2[s2base + (long long)t * Nn];
        v = (v + qbs[t]) * scale;
        vals[t] = v;
        m = fmaxf(m, v);
    }
    float s = 0.f;
    #pragma unroll 8
    for (int t = 0; t < Tt; t++) {
        float e = expf(vals[t] - m);
        vals[t] = e;
        s += e;
    }
    float inv = (j == i) ? 0.f : (1.f / s);

    #pragma unroll 8
    for (int t = 0; t < Tt; t++) {
        float w = vals[t] * inv;
        S1[s1base + (long long)t * (Nn * Nn)] = w;
        float r = w;
        #pragma unroll
        for (int o = 16; o; o >>= 1) r += __shfl_xor_sync(0xffffffffu, r, o);
        if (lane == 0) part[warp][t] = r;
    }
    __syncthreads();

    if (j < Tt) {
        float tot = 0.f;
        #pragma unroll
        for (int w = 0; w < 8; w++) tot += part[w][j];
        ws[qbbase + j] = tot;
    }
}

// ---------------- fused epilogue + LayerNorm ----------------------------------
__global__ void __launch_bounds__(128) final_kernel(
    const float* __restrict__ H,  const float* __restrict__ A,
    const float* __restrict__ z2, const float* __restrict__ Ct,
    const float* __restrict__ ws, const float* __restrict__ bf,
    const float* __restrict__ gamma, const float* __restrict__ beta,
    float* __restrict__ out)
{
    int row = blockIdx.x;
    int e = threadIdx.x;
    long long off = (long long)row * Dd + e;
    float s = ws[row];
    float x = H[off] + (A[off] + bf[e]) * s + z2[off] + Ct[off];

    float sum = x, sq = x * x;
    #pragma unroll
    for (int o = 16; o; o >>= 1) {
        sum += __shfl_xor_sync(0xffffffffu, sum, o);
        sq  += __shfl_xor_sync(0xffffffffu, sq,  o);
    }
    __shared__ float sm[4], sm2[4];
    int w = e >> 5;
    if ((e & 31) == 0) { sm[w] = sum; sm2[w] = sq; }
    __syncthreads();
    sum = sm[0] + sm[1] + sm[2] + sm[3];
    sq  = sm2[0] + sm2[1] + sm2[2] + sm2[3];
    float mu  = sum * (1.f / Dd);
    float var = sq * (1.f / Dd) - mu * mu;
    out[off] = (x - mu) * rsqrtf(var + 1e-5f) * gamma[e] + beta[e];
}

// ---------------- host helpers -------------------------------------------------
static void run_tf32(bool bt,
    const float* A, long long aS1, long long aS2, int aDiv, int lda,
    const float* B, long long bS1, long long bS2, int bDiv, int ldb,
    float* C, long long cS1, long long cS2, int cDiv, int ldc,
    int M, int N, int K, const float* bias, int batches)
{
    dim3 g(N / 128, M / 128, batches), blk(256);
    if (bt)
        gemm_tf32_kernel<true><<<g, blk>>>(A, aS1, aS2, aDiv, lda, B, bS1, bS2, bDiv, ldb,
                                           C, cS1, cS2, cDiv, ldc, K, bias);
    else
        gemm_tf32_kernel<false><<<g, blk>>>(A, aS1, aS2, aDiv, lda, B, bS1, bS2, bDiv, ldb,
                                            C, cS1, cS2, cDiv, ldc, K, bias);
}

static void run_gemm64(bool bt,
    const float* A, long long aS1, long long aS2, int aDiv, int lda,
    const float* B, long long bS1, long long bS2, int bDiv, int ldb,
    float* C, long long cS1, long long cS2, int cDiv, int ldc,
    int M, int N, int K, const float* bias, int batches)
{
    dim3 g((N + 63) / 64, (M + 63) / 64, batches), blk(256);
    if (bt)
        gemm_kernel<true><<<g, blk>>>(A, aS1, aS2, aDiv, lda, B, bS1, bS2, bDiv, ldb,
                                      C, cS1, cS2, cDiv, ldc, M, N, K, bias);
    else
        gemm_kernel<false><<<g, blk>>>(A, aS1, aS2, aDiv, lda, B, bS1, bS2, bDiv, ldb,
                                       C, cS1, cS2, cDiv, ldc, M, N, K, bias);
}

extern "C" void kernel_launch(void* const* d_in, const int* /*in_sizes*/, int /*n_in*/,
                              void* d_out, int /*out_size*/)
{
    const float* H   = (const float*)d_in[0];
    const float* R   = (const float*)d_in[1];
    const float* dH  = (const float*)d_in[2];
    const float* Wq  = (const float*)d_in[3];
    const float* bq  = (const float*)d_in[4];
    const float* Wk  = (const float*)d_in[5];
    const float* bk  = (const float*)d_in[6];
    const float* Wr  = (const float*)d_in[7];
    const float* br  = (const float*)d_in[8];
    const float* Wf  = (const float*)d_in[9];
    const float* bf  = (const float*)d_in[10];
    const float* gamma = (const float*)d_in[11];
    const float* beta  = (const float*)d_in[12];
    float* out = (float*)d_out;

    float *q_p, *k_p, *A_p, *B_p, *S1_p, *S2_p, *z2_p, *P_p, *qr_p, *qb_p, *Ct_p, *ws_p, *SdH_p, *Ej_p;
    cudaGetSymbolAddress((void**)&q_p,  g_q);
    cudaGetSymbolAddress((void**)&k_p,  g_k);
    cudaGetSymbolAddress((void**)&A_p,  g_A);
    cudaGetSymbolAddress((void**)&B_p,  g_Bj);
    cudaGetSymbolAddress((void**)&S1_p, g_S1);
    cudaGetSymbolAddress((void**)&S2_p, g_S2);
    cudaGetSymbolAddress((void**)&z2_p, g_z2);
    cudaGetSymbolAddress((void**)&P_p,  g_P);
    cudaGetSymbolAddress((void**)&qr_p, g_qr);
    cudaGetSymbolAddress((void**)&qb_p, g_qb);
    cudaGetSymbolAddress((void**)&Ct_p, g_Ct);
    cudaGetSymbolAddress((void**)&ws_p, g_ws);
    cudaGetSymbolAddress((void**)&SdH_p,g_SdH);
    cudaGetSymbolAddress((void**)&Ej_p, g_Ej);

    const int MROW = Bb * Nn * Tt;           // 65536
    const int WFLD = 3 * Dd + DRr;           // 416

    // 1-4. q, k, A, Bj  (H @ W^T)  — tensor core TF32
    run_tf32(true, H,0,0,1,Dd,  Wq,0,0,1,Dd,       q_p,0,0,1,DHh, MROW,DHh,Dd, bq, 1);
    run_tf32(true, H,0,0,1,Dd,  Wk,0,0,1,Dd,       k_p,0,0,1,DHh, MROW,DHh,Dd, bk, 1);
    run_tf32(true, H,0,0,1,Dd,  Wf,0,0,1,WFLD,     A_p,0,0,1,Dd,  MROW,Dd,Dd, nullptr, 1);
    run_tf32(true, H,0,0,1,Dd,  Wf+Dd,0,0,1,WFLD,  B_p,0,0,1,Dd,  MROW,Dd,Dd, nullptr, 1);

    // 5. qr = q @ Wr,  qb = q . br
    run_gemm64(false, q_p,0,0,1,DHh, Wr,0,0,1,DRr, qr_p,0,0,1,DRr, MROW,DRr,DHh, nullptr, 1);
    qb_kernel<<<MROW/8, 256>>>(q_p, br, qb_p);

    // 6-8. Ej = (sum_t dH) @ W4^T, folded into Bj
    sdh_kernel<<<Bb*Nn, Dd>>>(dH, SdH_p);
    run_tf32(true, SdH_p,0,0,1,Dd, Wf+2*Dd+DRr,0,0,1,WFLD, Ej_p,0,0,1,Dd, Bb*Nn,Dd,Dd, nullptr, 1);
    addej_kernel<<<(Bb*Nn*Tt*Dd)/256, 256>>>(B_p, Ej_p, Bb*Nn*Tt*Dd);

    // 9. S1[b,t,i,j] = q k^T   (batched over b,t) — TF32
    run_tf32(true, q_p,(long long)Nn*Tt*DHh,DHh,Tt, Tt*DHh,
                   k_p,(long long)Nn*Tt*DHh,DHh,Tt, Tt*DHh,
                   S1_p,(long long)Nn*Nn,0,1, Nn,
                   Nn,Nn,DHh, nullptr, Bb*Tt);

    // 10. S2[b,i,t,j] = qr @ R^T (batched over b,i)
    run_gemm64(true, qr_p,(long long)Tt*DRr,0,1, DRr,
                     R,(long long)Nn*DRr,0,1, DRr,
                     S2_p,(long long)Tt*Nn,0,1, Nn,
                     Tt,Nn,DRr, nullptr, Bb*Nn);

    // 11. fused softmax (adds qb) + diag mask + wsum; w overwrites S1
    softmax_fused_kernel<<<dim3(Nn, Bb), 256>>>(S1_p, S2_p, qb_p, ws_p);

    // 13. z2[b,i,t,e] = sum_j w * (Bj+Ej)    (batched over b,t) — TF32
    run_tf32(false, S1_p,(long long)Nn*Nn,0,1, Nn,
                    B_p,(long long)Nn*Tt*Dd,Dd,Tt, Tt*Dd,
                    z2_p,(long long)Nn*Tt*Dd,Dd,Tt, Tt*Dd,
                    Nn,Dd,Nn, nullptr, Bb*Tt);

    // 14. P[b,i,t,r] = sum_j w * R           (batched over b,i)
    run_gemm64(false, S1_p,(long long)Tt*Nn*Nn,Nn,Nn, Nn*Nn,
                      R,(long long)Nn*DRr,0,1, DRr,
                      P_p,(long long)Tt*DRr,0,1, DRr,
                      Tt,DRr,Nn, nullptr, Bb*Nn);

    // 15. Cterm = P @ W3^T — TF32
    run_tf32(true, P_p,0,0,1,DRr, Wf+2*Dd,0,0,1,WFLD, Ct_p,0,0,1,Dd, MROW,Dd,DRr, nullptr, 1);

    // 16. fused epilogue + LayerNorm
    final_kernel<<<MROW, Dd>>>(H, A_p, z2_p, Ct_p, ws_p, bf, gamma, beta, out);
}

// round 5
// speedup vs baseline: 2.5740x; 1.2784x over previous
#include <cuda_runtime.h>
#include <math.h>
#include <stdint.h>

// Shapes (fixed per problem)
#define Bb 4
#define Nn 256
#define Tt 64
#define Dd 128
#define DRr 32
#define DHh 128

#define MROWS (Bb*Nn*Tt)        // 65536
#define WFLD  (3*Dd + DRr)      // 416

// ---------------- scratch (device globals; no allocation allowed) -------------
__device__ float g_qkab[MROWS * 512];   // (b,i,t)x[q(128)|k(128)|A(128)|Bj(128)] 134MB
__device__ float g_S1[Bb*Tt*Nn*Nn];     // (b,t,i,j)  scores1, then w
__device__ float g_S2[Bb*Nn*Tt*Nn];     // (b,i,t,j)  scores2
__device__ float g_z2[Bb*Nn*Tt*Dd];     // (b,i,t,e)
__device__ float g_P [MROWS*DRr];       // (b,i,t,r)
__device__ float g_qr[MROWS*64];        // (b,i,t)x[qr(32)|qb(1)|pad]
__device__ float g_Ct[Bb*Nn*Tt*Dd];     // (b,i,t,e)
__device__ float g_ws[Bb*Nn*Tt];        // (b,i,t)
__device__ float g_SdH[Bb*Nn*Dd];       // (b,j,d)
__device__ float g_Ej[Bb*Nn*Dd];        // (b,j,e)
__device__ float g_Wcat[512*128];       // packed [Wq;Wk;W1;W2] row-major [n][d]
__device__ float g_bcat[512];           // packed [bq;bk;0;0]
__device__ float g_Wrcat[128*64];       // [h][r]: Wr cols 0..31, br at col 32, 0 pad

// ---------------- tf32 helpers -------------------------------------------------
__device__ __forceinline__ uint32_t f2tf(float x) {
    uint32_t r;
    asm("cvt.rna.tf32.f32 %0, %1;" : "=r"(r) : "f"(x));
    return r;
}

__device__ __forceinline__ void mma_tf32(float* d, const uint32_t* a, const uint32_t* b) {
    asm volatile(
        "mma.sync.aligned.m16n8k8.row.col.f32.tf32.tf32.f32 "
        "{%0,%1,%2,%3}, {%4,%5,%6,%7}, {%8,%9}, {%0,%1,%2,%3};"
        : "+f"(d[0]), "+f"(d[1]), "+f"(d[2]), "+f"(d[3])
        : "r"(a[0]), "r"(a[1]), "r"(a[2]), "r"(a[3]), "r"(b[0]), "r"(b[1]));
}

// =============== 128x128xK TF32 GEMM, double-buffered ========================
// Requires M%128==0, N%128==0, K%32==0. C = A @ (BT? B^T : B) + bias
// Dynamic smem: 2*(128*36 + 128*36)*4 = 73728 bytes.
#define TBUF 4608   // 128*36 u32 per buffer

template<bool BT>
__global__ void __launch_bounds__(256) gemm_tf32_kernel(
    const float* __restrict__ Ag, long long aS1, long long aS2, int aDiv, int lda,
    const float* __restrict__ Bg, long long bS1, long long bS2, int bDiv, int ldb,
    float*       __restrict__ Cg, long long cS1, long long cS2, int cDiv, int ldc,
    int K, const float* __restrict__ bias)
{
    extern __shared__ uint32_t sm[];
    uint32_t* As = sm;               // [2][TBUF]
    uint32_t* Bs = sm + 2 * TBUF;    // [2][TBUF] (nonT uses 32*136=4352 of it)

    int z = blockIdx.z;
    const float* A = Ag + (long long)(z / aDiv) * aS1 + (long long)(z % aDiv) * aS2;
    const float* B = Bg + (long long)(z / bDiv) * bS1 + (long long)(z % bDiv) * bS2;
    float*       C = Cg + (long long)(z / cDiv) * cS1 + (long long)(z % cDiv) * cS2;

    int bm = blockIdx.y * 128, bn = blockIdx.x * 128;
    int tid  = threadIdx.x;
    int warp = tid >> 5, lane = tid & 31;
    int gid = lane >> 2, tig = lane & 3;
    int wm = (warp & 1) * 64;
    int wn = (warp >> 1) * 32;

    int lr = tid >> 3;              // 0..31
    int lc = (tid & 7) * 4;         // 0..28
    int kr = tid >> 5;              // 0..7   (nonT B)
    int nc = (tid & 31) * 4;        // 0..124 (nonT B)

    float4 va[4], vb[4];
    float acc[4][4][4] = {};

    // ---- prologue: load k0=0, store to buf 0
    #pragma unroll
    for (int p = 0; p < 4; p++)
        va[p] = *reinterpret_cast<const float4*>(A + (long long)(bm + p * 32 + lr) * lda + lc);
    if (BT) {
        #pragma unroll
        for (int p = 0; p < 4; p++)
            vb[p] = *reinterpret_cast<const float4*>(B + (long long)(bn + p * 32 + lr) * ldb + lc);
    } else {
        #pragma unroll
        for (int p = 0; p < 4; p++)
            vb[p] = *reinterpret_cast<const float4*>(B + (long long)(p * 8 + kr) * ldb + bn + nc);
    }
    #pragma unroll
    for (int p = 0; p < 4; p++) {
        int row = p * 32 + lr;
        As[row * 36 + lc + 0] = f2tf(va[p].x);
        As[row * 36 + lc + 1] = f2tf(va[p].y);
        As[row * 36 + lc + 2] = f2tf(va[p].z);
        As[row * 36 + lc + 3] = f2tf(va[p].w);
        if (BT) {
            Bs[row * 36 + lc + 0] = f2tf(vb[p].x);
            Bs[row * 36 + lc + 1] = f2tf(vb[p].y);
            Bs[row * 36 + lc + 2] = f2tf(vb[p].z);
            Bs[row * 36 + lc + 3] = f2tf(vb[p].w);
        } else {
            int kk = p * 8 + kr;
            Bs[kk * 136 + nc + 0] = f2tf(vb[p].x);
            Bs[kk * 136 + nc + 1] = f2tf(vb[p].y);
            Bs[kk * 136 + nc + 2] = f2tf(vb[p].z);
            Bs[kk * 136 + nc + 3] = f2tf(vb[p].w);
        }
    }
    __syncthreads();

    int buf = 0;
    for (int k0 = 0; k0 < K; k0 += 32) {
        bool has_next = (k0 + 32 < K);
        // ---- issue next tile's global loads early
        if (has_next) {
            int kn = k0 + 32;
            #pragma unroll
            for (int p = 0; p < 4; p++)
                va[p] = *reinterpret_cast<const float4*>(A + (long long)(bm + p * 32 + lr) * lda + kn + lc);
            if (BT) {
                #pragma unroll
                for (int p = 0; p < 4; p++)
                    vb[p] = *reinterpret_cast<const float4*>(B + (long long)(bn + p * 32 + lr) * ldb + kn + lc);
            } else {
                #pragma unroll
                for (int p = 0; p < 4; p++)
                    vb[p] = *reinterpret_cast<const float4*>(B + (long long)(kn + p * 8 + kr) * ldb + bn + nc);
            }
        }
        // ---- compute from current buffer
        const uint32_t* Asb = As + buf * TBUF;
        const uint32_t* Bsb = Bs + buf * TBUF;
        #pragma unroll
        for (int ks = 0; ks < 4; ks++) {
            uint32_t af[4][4];
            #pragma unroll
            for (int mi = 0; mi < 4; mi++) {
                int r0 = wm + mi * 16 + gid;
                af[mi][0] = Asb[r0 * 36 + ks * 8 + tig];
                af[mi][1] = Asb[(r0 + 8) * 36 + ks * 8 + tig];
                af[mi][2] = Asb[r0 * 36 + ks * 8 + tig + 4];
                af[mi][3] = Asb[(r0 + 8) * 36 + ks * 8 + tig + 4];
            }
            uint32_t bfr[4][2];
            #pragma unroll
            for (int ni = 0; ni < 4; ni++) {
                int n0 = wn + ni * 8 + gid;
                if (BT) {
                    bfr[ni][0] = Bsb[n0 * 36 + ks * 8 + tig];
                    bfr[ni][1] = Bsb[n0 * 36 + ks * 8 + tig + 4];
                } else {
                    bfr[ni][0] = Bsb[(ks * 8 + tig) * 136 + n0];
                    bfr[ni][1] = Bsb[(ks * 8 + tig + 4) * 136 + n0];
                }
            }
            #pragma unroll
            for (int mi = 0; mi < 4; mi++)
                #pragma unroll
                for (int ni = 0; ni < 4; ni++)
                    mma_tf32(acc[mi][ni], af[mi], bfr[ni]);
        }
        // ---- store next tile into other buffer
        if (has_next) {
            uint32_t* Asn = As + (buf ^ 1) * TBUF;
            uint32_t* Bsn = Bs + (buf ^ 1) * TBUF;
            #pragma unroll
            for (int p = 0; p < 4; p++) {
                int row = p * 32 + lr;
                Asn[row * 36 + lc + 0] = f2tf(va[p].x);
                Asn[row * 36 + lc + 1] = f2tf(va[p].y);
                Asn[row * 36 + lc + 2] = f2tf(va[p].z);
                Asn[row * 36 + lc + 3] = f2tf(va[p].w);
                if (BT) {
                    Bsn[row * 36 + lc + 0] = f2tf(vb[p].x);
                    Bsn[row * 36 + lc + 1] = f2tf(vb[p].y);
                    Bsn[row * 36 + lc + 2] = f2tf(vb[p].z);
                    Bsn[row * 36 + lc + 3] = f2tf(vb[p].w);
                } else {
                    int kk = p * 8 + kr;
                    Bsn[kk * 136 + nc + 0] = f2tf(vb[p].x);
                    Bsn[kk * 136 + nc + 1] = f2tf(vb[p].y);
                    Bsn[kk * 136 + nc + 2] = f2tf(vb[p].z);
                    Bsn[kk * 136 + nc + 3] = f2tf(vb[p].w);
                }
            }
            __syncthreads();
            buf ^= 1;
        }
    }

    // ---- epilogue
    #pragma unroll
    for (int mi = 0; mi < 4; mi++) {
        int row0 = bm + wm + mi * 16 + gid;
        #pragma unroll
        for (int ni = 0; ni < 4; ni++) {
            int col = bn + wn + ni * 8 + tig * 2;
            float2 v0 = make_float2(acc[mi][ni][0], acc[mi][ni][1]);
            float2 v1 = make_float2(acc[mi][ni][2], acc[mi][ni][3]);
            if (bias) {
                float b0 = bias[col], b1 = bias[col + 1];
                v0.x += b0; v0.y += b1;
                v1.x += b0; v1.y += b1;
            }
            *reinterpret_cast<float2*>(C + (long long)row0 * ldc + col) = v0;
            *reinterpret_cast<float2*>(C + (long long)(row0 + 8) * ldc + col) = v1;
        }
    }
}

// =============== 64x32xK TF32 GEMM (small shapes; M%64, N%32, K%32) ==========
template<bool BT>
__global__ void __launch_bounds__(128) gemm_tf32s_kernel(
    const float* __restrict__ Ag, long long aS1, long long aS2, int aDiv, int lda,
    const float* __restrict__ Bg, long long bS1, long long bS2, int bDiv, int ldb,
    float*       __restrict__ Cg, long long cS1, long long cS2, int cDiv, int ldc,
    int K)
{
    __shared__ uint32_t As[64 * 36];
    __shared__ uint32_t Bs[32 * 40];

    int z = blockIdx.z;
    const float* A = Ag + (long long)(z / aDiv) * aS1 + (long long)(z % aDiv) * aS2;
    const float* B = Bg + (long long)(z / bDiv) * bS1 + (long long)(z % bDiv) * bS2;
    float*       C = Cg + (long long)(z / cDiv) * cS1 + (long long)(z % cDiv) * cS2;

    int bm = blockIdx.y * 64, bn = blockIdx.x * 32;
    int tid  = threadIdx.x;
    int warp = tid >> 5, lane = tid & 31;
    int gid = lane >> 2, tig = lane & 3;
    int wm = (warp & 1) * 32;
    int wn = (warp >> 1) * 16;

    int ar = tid >> 1, ac = (tid & 1) * 4;   // A loader: 64 rows x 8-col quads/2
    int br_ = tid >> 2, bc = (tid & 3) * 4;  // B loader: 32 rows x 16-col quads/4

    float acc[2][2][4] = {};

    for (int k0 = 0; k0 < K; k0 += 32) {
        #pragma unroll
        for (int p = 0; p < 4; p++) {
            int kq = ac + p * 8;
            float4 v = *reinterpret_cast<const float4*>(A + (long long)(bm + ar) * lda + k0 + kq);
            As[ar * 36 + kq + 0] = f2tf(v.x);
            As[ar * 36 + kq + 1] = f2tf(v.y);
            As[ar * 36 + kq + 2] = f2tf(v.z);
            As[ar * 36 + kq + 3] = f2tf(v.w);
        }
        if (BT) {
            #pragma unroll
            for (int p = 0; p < 2; p++) {
                int kq = bc + p * 16;
                float4 v = *reinterpret_cast<const float4*>(B + (long long)(bn + br_) * ldb + k0 + kq);
                Bs[br_ * 36 + kq + 0] = f2tf(v.x);
                Bs[br_ * 36 + kq + 1] = f2tf(v.y);
                Bs[br_ * 36 + kq + 2] = f2tf(v.z);
                Bs[br_ * 36 + kq + 3] = f2tf(v.w);
            }
        } else {
            #pragma unroll
            for (int p = 0; p < 2; p++) {
                int nq = bc + p * 16;
                float4 v = *reinterpret_cast<const float4*>(B + (long long)(k0 + br_) * ldb + bn + nq);
                Bs[br_ * 40 + nq + 0] = f2tf(v.x);
                Bs[br_ * 40 + nq + 1] = f2tf(v.y);
                Bs[br_ * 40 + nq + 2] = f2tf(v.z);
                Bs[br_ * 40 + nq + 3] = f2tf(v.w);
            }
        }
        __syncthreads();

        #pragma unroll
        for (int ks = 0; ks < 4; ks++) {
            uint32_t af[2][4];
            #pragma unroll
            for (int mi = 0; mi < 2; mi++) {
                int r0 = wm + mi * 16 + gid;
                af[mi][0] = As[r0 * 36 + ks * 8 + tig];
                af[mi][1] = As[(r0 + 8) * 36 + ks * 8 + tig];
                af[mi][2] = As[r0 * 36 + ks * 8 + tig + 4];
                af[mi][3] = As[(r0 + 8) * 36 + ks * 8 + tig + 4];
            }
            uint32_t bfr[2][2];
            #pragma unroll
            for (int ni = 0; ni < 2; ni++) {
                int n0 = wn + ni * 8 + gid;
                if (BT) {
                    bfr[ni][0] = Bs[n0 * 36 + ks * 8 + tig];
                    bfr[ni][1] = Bs[n0 * 36 + ks * 8 + tig + 4];
                } else {
                    bfr[ni][0] = Bs[(ks * 8 + tig) * 40 + n0];
                    bfr[ni][1] = Bs[(ks * 8 + tig + 4) * 40 + n0];
                }
            }
            #pragma unroll
            for (int mi = 0; mi < 2; mi++)
                #pragma unroll
                for (int ni = 0; ni < 2; ni++)
                    mma_tf32(acc[mi][ni], af[mi], bfr[ni]);
        }
        __syncthreads();
    }

    #pragma unroll
    for (int mi = 0; mi < 2; mi++) {
        int row0 = bm + wm + mi * 16 + gid;
        #pragma unroll
        for (int ni = 0; ni < 2; ni++) {
            int col = bn + wn + ni * 8 + tig * 2;
            *reinterpret_cast<float2*>(C + (long long)row0 * ldc + col) =
                make_float2(acc[mi][ni][0], acc[mi][ni][1]);
            *reinterpret_cast<float2*>(C + (long long)(row0 + 8) * ldc + col) =
                make_float2(acc[mi][ni][2], acc[mi][ni][3]);
        }
    }
}

// ---------------- weight packing ----------------------------------------------
__global__ void pack_wcat_kernel(const float* __restrict__ Wq, const float* __restrict__ Wk,
                                 const float* __restrict__ Wf, const float* __restrict__ bq,
                                 const float* __restrict__ bk,
                                 float* __restrict__ Wcat, float* __restrict__ bcat)
{
    int n = blockIdx.x, d = threadIdx.x;
    float v;
    if (n < 128)      v = Wq[n * Dd + d];
    else if (n < 256) v = Wk[(n - 128) * Dd + d];
    else if (n < 384) v = Wf[(n - 256) * WFLD + d];
    else              v = Wf[(n - 384) * WFLD + Dd + d];
    Wcat[n * Dd + d] = v;
    if (d == 0) bcat[n] = (n < 128) ? bq[n] : (n < 256 ? bk[n - 128] : 0.f);
}

__global__ void pack_wr_kernel(const float* __restrict__ Wr, const float* __restrict__ br,
                               float* __restrict__ Wrcat)
{
    int h = blockIdx.x, r = threadIdx.x;  // 128 x 64
    float v = 0.f;
    if (r < DRr) v = Wr[h * DRr + r];
    else if (r == DRr) v = br[h];
    Wrcat[h * 64 + r] = v;
}

// ---------------- delta_H sum over t -----------------------------------------
__global__ void sdh_kernel(const float* __restrict__ dH, float* __restrict__ S)
{
    int bj = blockIdx.x;
    int d  = threadIdx.x;
    const float* p = dH + (long long)bj * Tt * Dd + d;
    float s = 0.f;
    #pragma unroll 8
    for (int t = 0; t < Tt; t++) s += p[t * Dd];
    S[bj * Dd + d] = s;
}

// ---------------- Bj(in qkab) += Ej (broadcast over t) ------------------------
__global__ void addej_kernel(float* __restrict__ qkab, const float* __restrict__ Ej)
{
    int idx = blockIdx.x * blockDim.x + threadIdx.x;   // MROWS*Dd threads
    int row = idx >> 7, e = idx & 127;
    qkab[(long long)row * 512 + 384 + e] += Ej[(row >> 6) * Dd + e];
}

// ---- fused softmax over t + diag mask + wsum; w overwrites S1 ----------------
__global__ void __launch_bounds__(256) softmax_fused_kernel(
    float* __restrict__ S1, const float* __restrict__ S2,
    const float* __restrict__ qr, float* __restrict__ ws)
{
    int i = blockIdx.x, b = blockIdx.y;
    int j = threadIdx.x;
    int warp = j >> 5, lane = j & 31;

    __shared__ float qbs[Tt];
    __shared__ float part[8][Tt];

    long long qbbase = (long long)(b * Nn + i) * Tt;
    if (j < Tt) qbs[j] = qr[(qbbase + j) * 64 + 32];
    __syncthreads();

    long long s1base = (long long)b * (Tt * Nn * Nn) + (long long)i * Nn + j;
    long long s2base = (long long)(b * Nn + i) * (Tt * Nn) + j;
    const float scale = 0.08838834764831845f;

    float vals[Tt];
    float m = -1e30f;
    #pragma unroll 8
    for (int t = 0; t < Tt; t++) {
        float v = S1[s1base + (long long)t * (Nn * Nn)] + S2[s2base + (long long)t * Nn];
        v = (v + qbs[t]) * scale;
        vals[t] = v;
        m = fmaxf(m, v);
    }
    float s = 0.f;
    #pragma unroll 8
    for (int t = 0; t < Tt; t++) {
        float e = expf(vals[t] - m);
        vals[t] = e;
        s += e;
    }
    float inv = (j == i) ? 0.f : (1.f / s);

    #pragma unroll 8
    for (int t = 0; t < Tt; t++) {
        float w = vals[t] * inv;
        S1[s1base + (long long)t * (Nn * Nn)] = w;
        float r = w;
        #pragma unroll
        for (int o = 16; o; o >>= 1) r += __shfl_xor_sync(0xffffffffu, r, o);
        if (lane == 0) part[warp][t] = r;
    }
    __syncthreads();

    if (j < Tt) {
        float tot = 0.f;
        #pragma unroll
        for (int w = 0; w < 8; w++) tot += part[w][j];
        ws[qbbase + j] = tot;
    }
}

// ---------------- fused epilogue + LayerNorm ----------------------------------
__global__ void __launch_bounds__(128) final_kernel(
    const float* __restrict__ H,  const float* __restrict__ qkab,
    const float* __restrict__ z2, const float* __restrict__ Ct,
    const float* __restrict__ ws, const float* __restrict__ bf,
    const float* __restrict__ gamma, const float* __restrict__ beta,
    float* __restrict__ out)
{
    int row = blockIdx.x;
    int e = threadIdx.x;
    long long off = (long long)row * Dd + e;
    float s = ws[row];
    float a = qkab[(long long)row * 512 + 256 + e];
    float x = H[off] + (a + bf[e]) * s + z2[off] + Ct[off];

    float sum = x, sq = x * x;
    #pragma unroll
    for (int o = 16; o; o >>= 1) {
        sum += __shfl_xor_sync(0xffffffffu, sum, o);
        sq  += __shfl_xor_sync(0xffffffffu, sq,  o);
    }
    __shared__ float smu[4], smv[4];
    int w = e >> 5;
    if ((e & 31) == 0) { smu[w] = sum; smv[w] = sq; }
    __syncthreads();
    sum = smu[0] + smu[1] + smu[2] + smu[3];
    sq  = smv[0] + smv[1] + smv[2] + smv[3];
    float mu  = sum * (1.f / Dd);
    float var = sq * (1.f / Dd) - mu * mu;
    out[off] = (x - mu) * rsqrtf(var + 1e-5f) * gamma[e] + beta[e];
}

// ---------------- host helpers -------------------------------------------------
#define DSMEM (2 * 2 * TBUF * 4)   // 73728 bytes

static void run_tf32(bool bt,
    const float* A, long long aS1, long long aS2, int aDiv, int lda,
    const float* B, long long bS1, long long bS2, int bDiv, int ldb,
    float* C, long long cS1, long long cS2, int cDiv, int ldc,
    int M, int N, int K, const float* bias, int batches)
{
    dim3 g(N / 128, M / 128, batches), blk(256);
    if (bt) {
        cudaFuncSetAttribute(gemm_tf32_kernel<true>,
                             cudaFuncAttributeMaxDynamicSharedMemorySize, DSMEM);
        gemm_tf32_kernel<true><<<g, blk, DSMEM>>>(A, aS1, aS2, aDiv, lda, B, bS1, bS2, bDiv, ldb,
                                                  C, cS1, cS2, cDiv, ldc, K, bias);
    } else {
        cudaFuncSetAttribute(gemm_tf32_kernel<false>,
                             cudaFuncAttributeMaxDynamicSharedMemorySize, DSMEM);
        gemm_tf32_kernel<false><<<g, blk, DSMEM>>>(A, aS1, aS2, aDiv, lda, B, bS1, bS2, bDiv, ldb,
                                                   C, cS1, cS2, cDiv, ldc, K, bias);
    }
}

static void run_tf32s(bool bt,
    const float* A, long long aS1, long long aS2, int aDiv, int lda,
    const float* B, long long bS1, long long bS2, int bDiv, int ldb,
    float* C, long long cS1, long long cS2, int cDiv, int ldc,
    int M, int N, int K, int batches)
{
    dim3 g(N / 32, M / 64, batches), blk(128);
    if (bt)
        gemm_tf32s_kernel<true><<<g, blk>>>(A, aS1, aS2, aDiv, lda, B, bS1, bS2, bDiv, ldb,
                                            C, cS1, cS2, cDiv, ldc, K);
    else
        gemm_tf32s_kernel<false><<<g, blk>>>(A, aS1, aS2, aDiv, lda, B, bS1, bS2, bDiv, ldb,
                                             C, cS1, cS2, cDiv, ldc, K);
}

extern "C" void kernel_launch(void* const* d_in, const int* /*in_sizes*/, int /*n_in*/,
                              void* d_out, int /*out_size*/)
{
    const float* H   = (const float*)d_in[0];
    const float* R   = (const float*)d_in[1];
    const float* dH  = (const float*)d_in[2];
    const float* Wq  = (const float*)d_in[3];
    const float* bq  = (const float*)d_in[4];
    const float* Wk  = (const float*)d_in[5];
    const float* bk  = (const float*)d_in[6];
    const float* Wr  = (const float*)d_in[7];
    const float* br  = (const float*)d_in[8];
    const float* Wf  = (const float*)d_in[9];
    const float* bf  = (const float*)d_in[10];
    const float* gamma = (const float*)d_in[11];
    const float* beta  = (const float*)d_in[12];
    float* out = (float*)d_out;

    float *qk_p, *S1_p, *S2_p, *z2_p, *P_p, *qr_p, *Ct_p, *ws_p, *SdH_p, *Ej_p,
          *Wc_p, *bc_p, *Wrc_p;
    cudaGetSymbolAddress((void**)&qk_p, g_qkab);
    cudaGetSymbolAddress((void**)&S1_p, g_S1);
    cudaGetSymbolAddress((void**)&S2_p, g_S2);
    cudaGetSymbolAddress((void**)&z2_p, g_z2);
    cudaGetSymbolAddress((void**)&P_p,  g_P);
    cudaGetSymbolAddress((void**)&qr_p, g_qr);
    cudaGetSymbolAddress((void**)&Ct_p, g_Ct);
    cudaGetSymbolAddress((void**)&ws_p, g_ws);
    cudaGetSymbolAddress((void**)&SdH_p,g_SdH);
    cudaGetSymbolAddress((void**)&Ej_p, g_Ej);
    cudaGetSymbolAddress((void**)&Wc_p, g_Wcat);
    cudaGetSymbolAddress((void**)&bc_p, g_bcat);
    cudaGetSymbolAddress((void**)&Wrc_p,g_Wrcat);

    // 0. pack weights
    pack_wcat_kernel<<<512, Dd>>>(Wq, Wk, Wf, bq, bk, Wc_p, bc_p);
    pack_wr_kernel<<<Dd, 64>>>(Wr, br, Wrc_p);

    // 1. fused projection: [q|k|A|Bj] = H @ Wcat^T + bcat   (M=65536, N=512, K=128)
    run_tf32(true, H,0,0,1,Dd, Wc_p,0,0,1,Dd, qk_p,0,0,1,512, MROWS,512,Dd, bc_p, 1);

    // 2. qr_ext = q @ Wrcat  (cols: qr 0..31, qb at 32)   (M=65536, N=64, K=128)
    run_tf32s(false, qk_p,0,0,1,512, Wrc_p,0,0,1,64, qr_p,0,0,1,64, MROWS,64,DHh, 1);

    // 3. Ej = (sum_t dH) @ W4^T, folded into Bj slice of qkab
    sdh_kernel<<<Bb*Nn, Dd>>>(dH, SdH_p);
    run_tf32(true, SdH_p,0,0,1,Dd, Wf+2*Dd+DRr,0,0,1,WFLD, Ej_p,0,0,1,Dd, Bb*Nn,Dd,Dd, nullptr, 1);
    addej_kernel<<<(MROWS*Dd)/256, 256>>>(qk_p, Ej_p);

    // 4. S1[b,t,i,j] = q k^T   (batched over b,t)
    run_tf32(true, qk_p,(long long)Nn*Tt*512,512,Tt, (long long)Tt*512,
                   qk_p+128,(long long)Nn*Tt*512,512,Tt, (long long)Tt*512,
                   S1_p,(long long)Nn*Nn,0,1, Nn,
                   Nn,Nn,DHh, nullptr, Bb*Tt);

    // 5. S2[b,i,t,j] = qr @ R^T (batched over b,i)
    run_tf32s(true, qr_p,(long long)Tt*64,0,1, 64,
                    R,(long long)Nn*DRr,0,1, DRr,
                    S2_p,(long long)Tt*Nn,0,1, Nn,
                    Tt,Nn,DRr, Bb*Nn);

    // 6. fused softmax (adds qb) + diag mask + wsum; w overwrites S1
    softmax_fused_kernel<<<dim3(Nn, Bb), 256>>>(S1_p, S2_p, qr_p, ws_p);

    // 7. z2[b,i,t,e] = sum_j w * (Bj+Ej)    (batched over b,t)
    run_tf32(false, S1_p,(long long)Nn*Nn,0,1, Nn,
                    qk_p+384,(long long)Nn*Tt*512,512,Tt, (long long)Tt*512,
                    z2_p,(long long)Nn*Tt*Dd,Dd,Tt, Tt*Dd,
                    Nn,Dd,Nn, nullptr, Bb*Tt);

    // 8. P[b,i,t,r] = sum_j w * R           (batched over b,i)
    run_tf32s(false, S1_p,(long long)Tt*Nn*Nn,Nn,Nn, (long long)Nn*Nn,
                     R,(long long)Nn*DRr,0,1, DRr,
                     P_p,(long long)Tt*DRr,0,1, DRr,
                     Tt,DRr,Nn, Bb*Nn);

    // 9. Cterm = P @ W3^T
    run_tf32(true, P_p,0,0,1,DRr, Wf+2*Dd,0,0,1,WFLD, Ct_p,0,0,1,Dd, MROWS,Dd,DRr, nullptr, 1);

    // 10. fused epilogue + LayerNorm
    final_kernel<<<MROWS, Dd>>>(H, qk_p, z2_p, Ct_p, ws_p, bf, gamma, beta, out);
}